// round 7
// baseline (speedup 1.0000x reference)
#include <cuda_runtime.h>
#include <cuda_bf16.h>
#include <cstdint>

// ---------------------------------------------------------------------------
// Problem constants
// ---------------------------------------------------------------------------
#define BDIM 4096
#define LDIM 4096
#define HDIM 1024

// GEMM tiling: CTA tile 128x128, 4 warps of 64x64, BK=32, 3 stages
#define BM 128
#define BN 128
#define BK 32
#define KT_CNT (HDIM / BK)        // 32 k-chunks
#define STAGES 3
#define TILE_BYTES (BM * BK * 4)  // 16384 B (unpadded, 128B rows)
#define STAGE_BYTES (2 * TILE_BYTES)          // A + B
#define SMEM_BYTES (STAGES * STAGE_BYTES)     // 98304 B -> 2 CTAs/SM

// ---------------------------------------------------------------------------
// Device scratch: pre-converted tf32 (fp32 bit patterns), k pair-permuted
// within each 8-group: [0,4,1,5,2,6,3,7]
// ---------------------------------------------------------------------------
__device__ float g_diag[LDIM];
__device__ uint32_t g_x32[BDIM * HDIM];
__device__ uint32_t g_w32[LDIM * HDIM];

// ---------------------------------------------------------------------------
// Helpers
// ---------------------------------------------------------------------------
__device__ __forceinline__ uint32_t f2tf32(float x) {
    uint32_t r;
    asm volatile("cvt.rna.tf32.f32 %0, %1;\n" : "=r"(r) : "f"(x));
    return r;
}

__device__ __forceinline__ void mma_tf32(float& c0, float& c1, float& c2, float& c3,
                                         uint32_t a0, uint32_t a1, uint32_t a2, uint32_t a3,
                                         uint32_t b0, uint32_t b1) {
    asm volatile(
        "mma.sync.aligned.m16n8k8.row.col.f32.tf32.tf32.f32 "
        "{%0,%1,%2,%3}, {%4,%5,%6,%7}, {%8,%9}, {%0,%1,%2,%3};\n"
        : "+f"(c0), "+f"(c1), "+f"(c2), "+f"(c3)
        : "r"(a0), "r"(a1), "r"(a2), "r"(a3), "r"(b0), "r"(b1));
}

__device__ __forceinline__ void cp_async16(void* smem_ptr, const void* gptr) {
    uint32_t saddr = (uint32_t)__cvta_generic_to_shared(smem_ptr);
    asm volatile("cp.async.cg.shared.global [%0], [%1], 16;\n" :: "r"(saddr), "l"(gptr));
}
__device__ __forceinline__ void cp_commit() {
    asm volatile("cp.async.commit_group;\n" ::: "memory");
}
template <int N>
__device__ __forceinline__ void cp_wait() {
    asm volatile("cp.async.wait_group %0;\n" :: "n"(N) : "memory");
}

// ---------------------------------------------------------------------------
// Kernel 1a/1b: fp32 -> tf32 bits, with k pair-permutation within 8-groups.
// ---------------------------------------------------------------------------
__device__ __forceinline__ void convert_group(const float* __restrict__ src,
                                              uint32_t* __restrict__ dst, size_t gi) {
    const float4 v0 = reinterpret_cast<const float4*>(src)[2 * gi + 0];  // k 0..3
    const float4 v1 = reinterpret_cast<const float4*>(src)[2 * gi + 1];  // k 4..7
    uint4 o0, o1;
    o0.x = f2tf32(v0.x);  o0.y = f2tf32(v1.x);   // 0,4
    o0.z = f2tf32(v0.y);  o0.w = f2tf32(v1.y);   // 1,5
    o1.x = f2tf32(v0.z);  o1.y = f2tf32(v1.z);   // 2,6
    o1.z = f2tf32(v0.w);  o1.w = f2tf32(v1.w);   // 3,7
    reinterpret_cast<uint4*>(dst)[2 * gi + 0] = o0;
    reinterpret_cast<uint4*>(dst)[2 * gi + 1] = o1;
}

__global__ void convert_x_kernel(const float* __restrict__ src) {
    size_t gi = (size_t)blockIdx.x * blockDim.x + threadIdx.x;  // over N/8
    convert_group(src, g_x32, gi);
}
__global__ void convert_w_kernel(const float* __restrict__ src) {
    size_t gi = (size_t)blockIdx.x * blockDim.x + threadIdx.x;
    convert_group(src, g_w32, gi);
}

// ---------------------------------------------------------------------------
// Kernel 2: diag[j] = sum_k E[j,k]*W[j,k] + b[j]   (fp32 exact)
// ---------------------------------------------------------------------------
__global__ void diag_kernel(const float* __restrict__ E,
                            const float* __restrict__ W,
                            const float* __restrict__ b) {
    int warp = (blockIdx.x * blockDim.x + threadIdx.x) >> 5;
    int lane = threadIdx.x & 31;
    if (warp >= LDIM) return;
    const float4* e4 = reinterpret_cast<const float4*>(E + (size_t)warp * HDIM);
    const float4* w4 = reinterpret_cast<const float4*>(W + (size_t)warp * HDIM);
    float sum = 0.f;
#pragma unroll
    for (int i = 0; i < HDIM / 4 / 32; i++) {
        float4 e = e4[lane + i * 32];
        float4 w = w4[lane + i * 32];
        sum += e.x * w.x + e.y * w.y + e.z * w.z + e.w * w.w;
    }
#pragma unroll
    for (int o = 16; o > 0; o >>= 1)
        sum += __shfl_down_sync(0xffffffffu, sum, o);
    if (lane == 0) g_diag[warp] = sum + b[warp];
}

// ---------------------------------------------------------------------------
// Kernel 3: C[m,n] = sum_k X[m,k]*W[n,k] + diag[n]
// TF32 mma.sync, 4 warps x (64x64 warp tile), 3-stage cp.async,
// unpadded 128B rows with XOR group swizzle (conflict-free LDS.64).
// ---------------------------------------------------------------------------
__global__ void __launch_bounds__(128, 2)
gemm_tf32_kernel(float* __restrict__ C) {
    extern __shared__ char smem[];

    const int tid = threadIdx.x;
    const int lane = tid & 31;
    const int wid = tid >> 5;       // 0..3
    const int warp_m = wid >> 1;    // 0..1
    const int warp_n = wid & 1;     // 0..1

    const int m0 = blockIdx.y * BM;
    const int n0 = blockIdx.x * BN;

    const uint32_t* Ag = g_x32 + (size_t)m0 * HDIM;
    const uint32_t* Bg = g_w32 + (size_t)n0 * HDIM;

    // Stage loader: 128 rows x 8 chunks(16B) per tile, 128 threads -> 8 iters x2.
    auto load_stage = [&](int s, int kt) {
        char* as = smem + s * STAGE_BYTES;
        char* bs = as + TILE_BYTES;
        const int k0 = kt * BK;
#pragma unroll
        for (int j = 0; j < 8; j++) {
            int c = j * 128 + tid;        // 0..1023
            int row = c >> 3;             // 0..127
            int ch = c & 7;               // 16B chunk
            int g = ch >> 1, h = ch & 1;
            uint32_t dst = (uint32_t)(row * 128 + (((g ^ (row & 3)) << 1) | h) * 16);
            cp_async16(as + dst, Ag + (size_t)row * HDIM + k0 + ch * 4);
            cp_async16(bs + dst, Bg + (size_t)row * HDIM + k0 + ch * 4);
        }
        cp_commit();
    };

    float acc[32][4];
#pragma unroll
    for (int i = 0; i < 32; i++)
#pragma unroll
        for (int j = 0; j < 4; j++) acc[i][j] = 0.f;

    // Precomputed fragment base offsets (bits 5-6 hold the swizzle group)
    const int t2 = (lane & 3) * 8;
    uint32_t abase[4], bbase[8];
#pragma unroll
    for (int mt = 0; mt < 4; mt++) {
        int r = warp_m * 64 + mt * 16 + (lane >> 2);
        abase[mt] = (uint32_t)(r * 128 + ((r & 3) << 5) + t2);
    }
#pragma unroll
    for (int nt = 0; nt < 8; nt++) {
        int n = warp_n * 64 + nt * 8 + (lane >> 2);
        bbase[nt] = (uint32_t)(n * 128 + ((n & 3) << 5) + t2);
    }

    // Prologue
#pragma unroll
    for (int s = 0; s < STAGES - 1; s++) load_stage(s, s);

    for (int kt = 0; kt < KT_CNT; kt++) {
        cp_wait<STAGES - 2>();
        __syncthreads();

        if (kt + STAGES - 1 < KT_CNT)
            load_stage((kt + STAGES - 1) % STAGES, kt + STAGES - 1);
        else
            cp_commit();   // keep group count consistent

        const char* as = smem + (kt % STAGES) * STAGE_BYTES;
        const char* bs = as + TILE_BYTES;

#pragma unroll
        for (int ks = 0; ks < BK / 8; ks++) {
            const uint32_t xr = (uint32_t)(ks << 5);
            uint2 afr[4][2];   // [mt][0]=row r (a0,a2), [1]=row r+8 (a1,a3)
#pragma unroll
            for (int mt = 0; mt < 4; mt++) {
                uint32_t off = abase[mt] ^ xr;
                afr[mt][0] = *reinterpret_cast<const uint2*>(as + off);
                afr[mt][1] = *reinterpret_cast<const uint2*>(as + off + 8 * 128);
            }
            uint2 bfr[8];
#pragma unroll
            for (int nt = 0; nt < 8; nt++)
                bfr[nt] = *reinterpret_cast<const uint2*>(bs + (bbase[nt] ^ xr));
#pragma unroll
            for (int mt = 0; mt < 4; mt++)
#pragma unroll
                for (int nt = 0; nt < 8; nt++)
                    mma_tf32(acc[mt * 8 + nt][0], acc[mt * 8 + nt][1],
                             acc[mt * 8 + nt][2], acc[mt * 8 + nt][3],
                             afr[mt][0].x, afr[mt][1].x, afr[mt][0].y, afr[mt][1].y,
                             bfr[nt].x, bfr[nt].y);
        }
        __syncthreads();
    }

    // Epilogue: + diag[n], float2 stores
#pragma unroll
    for (int mt = 0; mt < 4; mt++) {
#pragma unroll
        for (int nt = 0; nt < 8; nt++) {
            int r = m0 + warp_m * 64 + mt * 16 + (lane >> 2);
            int c = n0 + warp_n * 64 + nt * 8 + 2 * (lane & 3);
            float2 dg = *reinterpret_cast<const float2*>(&g_diag[c]);
            float2 v0 = make_float2(acc[mt * 8 + nt][0] + dg.x,
                                    acc[mt * 8 + nt][1] + dg.y);
            float2 v1 = make_float2(acc[mt * 8 + nt][2] + dg.x,
                                    acc[mt * 8 + nt][3] + dg.y);
            *reinterpret_cast<float2*>(C + (size_t)r * LDIM + c) = v0;
            *reinterpret_cast<float2*>(C + (size_t)(r + 8) * LDIM + c) = v1;
        }
    }
}

// ---------------------------------------------------------------------------
// Launch
// ---------------------------------------------------------------------------
extern "C" void kernel_launch(void* const* d_in, const int* in_sizes, int n_in,
                              void* d_out, int out_size) {
    const float* x = (const float*)d_in[0];   // bert_output [B,H]
    const float* E = (const float*)d_in[1];   // label_embed [L,H]
    const float* W = (const float*)d_in[2];   // W [L,H]
    const float* b = (const float*)d_in[3];   // b [L]
    float* out = (float*)d_out;               // [B,L]

    convert_x_kernel<<<(BDIM * HDIM / 8) / 256, 256>>>(x);
    convert_w_kernel<<<(LDIM * HDIM / 8) / 256, 256>>>(W);
    diag_kernel<<<LDIM / 8, 256>>>(E, W, b);

    cudaFuncSetAttribute(gemm_tf32_kernel,
                         cudaFuncAttributeMaxDynamicSharedMemorySize, SMEM_BYTES);
    dim3 grid(LDIM / BN, BDIM / BM);
    gemm_tf32_kernel<<<grid, 128, SMEM_BYTES>>>(out);
}

// round 10
// speedup vs baseline: 1.7161x; 1.7161x over previous
#include <cuda_runtime.h>
#include <cuda_fp16.h>
#include <cstdint>

// ---------------------------------------------------------------------------
// Problem constants
// ---------------------------------------------------------------------------
#define BDIM 4096
#define LDIM 4096
#define HDIM 1024

// GEMM tiling: CTA tile 128x128, 4 warps of 64x64, BK=64 (fp16), 3 stages
#define BM 128
#define BN 128
#define BK 64
#define KT_CNT (HDIM / BK)        // 16 k-chunks
#define STAGES 3
#define TILE_BYTES (BM * BK * 2)  // 16384 B (128 rows x 128B)
#define STAGE_BYTES (2 * TILE_BYTES)          // A + B = 32768
#define SMEM_BYTES (STAGES * STAGE_BYTES)     // 98304 B -> 2 CTAs/SM

// ---------------------------------------------------------------------------
// Device scratch: pre-converted fp16, k pair-permuted within each 16-group:
// half2 pairs stored in order [p0,p4,p1,p5,p2,p6,p3,p7]
// (pair pi = elements (2i, 2i+1)); so LDS.64 at pair-slot 2t gives
// (k=2t,2t+1) and (k=2t+8,2t+9) — exactly (a0,a2)/(a1,a3)/(b0,b1).
// ---------------------------------------------------------------------------
__device__ float g_diag[LDIM];
__device__ __half g_xh[BDIM * HDIM];
__device__ __half g_wh[LDIM * HDIM];

// ---------------------------------------------------------------------------
// Helpers
// ---------------------------------------------------------------------------
__device__ __forceinline__ void mma_fp16(float& c0, float& c1, float& c2, float& c3,
                                         uint32_t a0, uint32_t a1, uint32_t a2, uint32_t a3,
                                         uint32_t b0, uint32_t b1) {
    asm volatile(
        "mma.sync.aligned.m16n8k16.row.col.f32.f16.f16.f32 "
        "{%0,%1,%2,%3}, {%4,%5,%6,%7}, {%8,%9}, {%0,%1,%2,%3};\n"
        : "+f"(c0), "+f"(c1), "+f"(c2), "+f"(c3)
        : "r"(a0), "r"(a1), "r"(a2), "r"(a3), "r"(b0), "r"(b1));
}

__device__ __forceinline__ void cp_async16(void* smem_ptr, const void* gptr) {
    uint32_t saddr = (uint32_t)__cvta_generic_to_shared(smem_ptr);
    asm volatile("cp.async.cg.shared.global [%0], [%1], 16;\n" :: "r"(saddr), "l"(gptr));
}
__device__ __forceinline__ void cp_commit() {
    asm volatile("cp.async.commit_group;\n" ::: "memory");
}
template <int N>
__device__ __forceinline__ void cp_wait() {
    asm volatile("cp.async.wait_group %0;\n" :: "n"(N) : "memory");
}

// ---------------------------------------------------------------------------
// Kernel 1a/1b: fp32 -> fp16, pair-permuted within 16-groups.
// Each thread: one 16-float group (4 float4 reads -> 2 uint4 writes).
// ---------------------------------------------------------------------------
__device__ __forceinline__ void convert16(const float* __restrict__ src,
                                          __half* __restrict__ dst, size_t gi) {
    const float4* s = reinterpret_cast<const float4*>(src) + 4 * gi;
    float4 v0 = s[0], v1 = s[1], v2 = s[2], v3 = s[3];
    uint32_t p[8];
    __half2 h;
    h = __floats2half2_rn(v0.x, v0.y); p[0] = *reinterpret_cast<uint32_t*>(&h);
    h = __floats2half2_rn(v0.z, v0.w); p[1] = *reinterpret_cast<uint32_t*>(&h);
    h = __floats2half2_rn(v1.x, v1.y); p[2] = *reinterpret_cast<uint32_t*>(&h);
    h = __floats2half2_rn(v1.z, v1.w); p[3] = *reinterpret_cast<uint32_t*>(&h);
    h = __floats2half2_rn(v2.x, v2.y); p[4] = *reinterpret_cast<uint32_t*>(&h);
    h = __floats2half2_rn(v2.z, v2.w); p[5] = *reinterpret_cast<uint32_t*>(&h);
    h = __floats2half2_rn(v3.x, v3.y); p[6] = *reinterpret_cast<uint32_t*>(&h);
    h = __floats2half2_rn(v3.z, v3.w); p[7] = *reinterpret_cast<uint32_t*>(&h);
    uint4 o0 = make_uint4(p[0], p[4], p[1], p[5]);   // pairs 0,4,1,5
    uint4 o1 = make_uint4(p[2], p[6], p[3], p[7]);   // pairs 2,6,3,7
    reinterpret_cast<uint4*>(dst)[2 * gi + 0] = o0;
    reinterpret_cast<uint4*>(dst)[2 * gi + 1] = o1;
}

__global__ void convert_x_kernel(const float* __restrict__ src) {
    size_t gi = (size_t)blockIdx.x * blockDim.x + threadIdx.x;   // over N/16
    convert16(src, g_xh, gi);
}
__global__ void convert_w_kernel(const float* __restrict__ src) {
    size_t gi = (size_t)blockIdx.x * blockDim.x + threadIdx.x;
    convert16(src, g_wh, gi);
}

// ---------------------------------------------------------------------------
// Kernel 2: diag[j] = sum_k E[j,k]*W[j,k] + b[j]   (fp32 exact)
// ---------------------------------------------------------------------------
__global__ void diag_kernel(const float* __restrict__ E,
                            const float* __restrict__ W,
                            const float* __restrict__ b) {
    int warp = (blockIdx.x * blockDim.x + threadIdx.x) >> 5;
    int lane = threadIdx.x & 31;
    if (warp >= LDIM) return;
    const float4* e4 = reinterpret_cast<const float4*>(E + (size_t)warp * HDIM);
    const float4* w4 = reinterpret_cast<const float4*>(W + (size_t)warp * HDIM);
    float sum = 0.f;
#pragma unroll
    for (int i = 0; i < HDIM / 4 / 32; i++) {
        float4 e = e4[lane + i * 32];
        float4 w = w4[lane + i * 32];
        sum += e.x * w.x + e.y * w.y + e.z * w.z + e.w * w.w;
    }
#pragma unroll
    for (int o = 16; o > 0; o >>= 1)
        sum += __shfl_down_sync(0xffffffffu, sum, o);
    if (lane == 0) g_diag[warp] = sum + b[warp];
}

// ---------------------------------------------------------------------------
// Kernel 3: C[m,n] = sum_k X[m,k]*W[n,k] + diag[n]
// fp16 mma.sync m16n8k16, 4 warps x (64x64), 3-stage cp.async, BK=64,
// unpadded 128B rows with XOR group swizzle (conflict-free LDS.64).
// ---------------------------------------------------------------------------
__global__ void __launch_bounds__(128, 2)
gemm_fp16_kernel(float* __restrict__ C) {
    extern __shared__ char smem[];

    const int tid = threadIdx.x;
    const int lane = tid & 31;
    const int wid = tid >> 5;       // 0..3
    const int warp_m = wid >> 1;    // 0..1
    const int warp_n = wid & 1;     // 0..1

    const int m0 = blockIdx.y * BM;
    const int n0 = blockIdx.x * BN;

    const __half* Ag = g_xh + (size_t)m0 * HDIM;
    const __half* Bg = g_wh + (size_t)n0 * HDIM;

    // Stage loader: per tile 128 rows x 8 chunks(16B); 128 threads -> 8 iters x2.
    // Row layout: 4 groups of 32B (one k16-group each, 4 half2 pairs).
    // Chunk ch = 2g+h. Swizzled dst group = g ^ (row & 3).
    auto load_stage = [&](int s, int kt) {
        char* as = smem + s * STAGE_BYTES;
        char* bs = as + TILE_BYTES;
        const int k0 = kt * BK;
#pragma unroll
        for (int j = 0; j < 8; j++) {
            int c = j * 128 + tid;        // 0..1023
            int row = c >> 3;             // 0..127
            int ch = c & 7;               // 16B chunk
            int g = ch >> 1, h = ch & 1;
            uint32_t dst = (uint32_t)(row * 128 + (((g ^ (row & 3)) << 1) | h) * 16);
            cp_async16(as + dst, Ag + (size_t)row * HDIM + k0 + ch * 8);
            cp_async16(bs + dst, Bg + (size_t)row * HDIM + k0 + ch * 8);
        }
        cp_commit();
    };

    float acc[32][4];
#pragma unroll
    for (int i = 0; i < 32; i++)
#pragma unroll
        for (int j = 0; j < 4; j++) acc[i][j] = 0.f;

    // Fragment base offsets (group field = bits [5:6]); t2 = pair slot 2t.
    const int t2 = (lane & 3) * 8;
    uint32_t abase[4], bbase[8];
#pragma unroll
    for (int mt = 0; mt < 4; mt++) {
        int r = warp_m * 64 + mt * 16 + (lane >> 2);
        abase[mt] = (uint32_t)(r * 128 + ((r & 3) << 5) + t2);
    }
#pragma unroll
    for (int nt = 0; nt < 8; nt++) {
        int n = warp_n * 64 + nt * 8 + (lane >> 2);
        bbase[nt] = (uint32_t)(n * 128 + ((n & 3) << 5) + t2);
    }

    // Prologue
#pragma unroll
    for (int s = 0; s < STAGES - 1; s++) load_stage(s, s);

    for (int kt = 0; kt < KT_CNT; kt++) {
        cp_wait<STAGES - 2>();
        __syncthreads();

        if (kt + STAGES - 1 < KT_CNT)
            load_stage((kt + STAGES - 1) % STAGES, kt + STAGES - 1);
        else
            cp_commit();   // keep group count consistent

        const char* as = smem + (kt % STAGES) * STAGE_BYTES;
        const char* bs = as + TILE_BYTES;

#pragma unroll
        for (int ks = 0; ks < BK / 16; ks++) {   // 4 k16-groups
            const uint32_t xr = (uint32_t)(ks << 5);
            uint2 afr[4][2];   // [mt][0] = row r -> (a0,a2); [1] = row r+8 -> (a1,a3)
#pragma unroll
            for (int mt = 0; mt < 4; mt++) {
                uint32_t off = abase[mt] ^ xr;
                afr[mt][0] = *reinterpret_cast<const uint2*>(as + off);
                afr[mt][1] = *reinterpret_cast<const uint2*>(as + off + 8 * 128);
            }
            uint2 bfr[8];      // (b0,b1)
#pragma unroll
            for (int nt = 0; nt < 8; nt++)
                bfr[nt] = *reinterpret_cast<const uint2*>(bs + (bbase[nt] ^ xr));
#pragma unroll
            for (int mt = 0; mt < 4; mt++)
#pragma unroll
                for (int nt = 0; nt < 8; nt++)
                    mma_fp16(acc[mt * 8 + nt][0], acc[mt * 8 + nt][1],
                             acc[mt * 8 + nt][2], acc[mt * 8 + nt][3],
                             afr[mt][0].x, afr[mt][1].x, afr[mt][0].y, afr[mt][1].y,
                             bfr[nt].x, bfr[nt].y);
        }
        __syncthreads();
    }

    // Epilogue: + diag[n], float2 stores
#pragma unroll
    for (int mt = 0; mt < 4; mt++) {
#pragma unroll
        for (int nt = 0; nt < 8; nt++) {
            int r = m0 + warp_m * 64 + mt * 16 + (lane >> 2);
            int c = n0 + warp_n * 64 + nt * 8 + 2 * (lane & 3);
            float2 dg = *reinterpret_cast<const float2*>(&g_diag[c]);
            float2 v0 = make_float2(acc[mt * 8 + nt][0] + dg.x,
                                    acc[mt * 8 + nt][1] + dg.y);
            float2 v1 = make_float2(acc[mt * 8 + nt][2] + dg.x,
                                    acc[mt * 8 + nt][3] + dg.y);
            *reinterpret_cast<float2*>(C + (size_t)r * LDIM + c) = v0;
            *reinterpret_cast<float2*>(C + (size_t)(r + 8) * LDIM + c) = v1;
        }
    }
}

// ---------------------------------------------------------------------------
// Launch
// ---------------------------------------------------------------------------
extern "C" void kernel_launch(void* const* d_in, const int* in_sizes, int n_in,
                              void* d_out, int out_size) {
    const float* x = (const float*)d_in[0];   // bert_output [B,H]
    const float* E = (const float*)d_in[1];   // label_embed [L,H]
    const float* W = (const float*)d_in[2];   // W [L,H]
    const float* b = (const float*)d_in[3];   // b [L]
    float* out = (float*)d_out;               // [B,L]

    convert_x_kernel<<<(BDIM * HDIM / 16) / 256, 256>>>(x);
    convert_w_kernel<<<(LDIM * HDIM / 16) / 256, 256>>>(W);
    diag_kernel<<<LDIM / 8, 256>>>(E, W, b);

    cudaFuncSetAttribute(gemm_fp16_kernel,
                         cudaFuncAttributeMaxDynamicSharedMemorySize, SMEM_BYTES);
    dim3 grid(LDIM / BN, BDIM / BM);
    gemm_fp16_kernel<<<grid, 128, SMEM_BYTES>>>(out);
}